// round 1
// baseline (speedup 1.0000x reference)
#include <cuda_runtime.h>
#include <cstdint>

// Problem constants (match reference)
#define NN      100000
#define EE      3200000
#define GAMMA   0.1f
#define EPSN    1e-12f

// out[i] = -gamma * v[i]   (initialize accumulator with damping term)
__global__ void init_damping_kernel(const float* __restrict__ v,
                                    float* __restrict__ out, int n) {
    int i = blockIdx.x * blockDim.x + threadIdx.x;
    if (i < n) {
        float2 vv = reinterpret_cast<const float2*>(v)[i];
        float2 o;
        o.x = -GAMMA * vv.x;
        o.y = -GAMMA * vv.y;
        reinterpret_cast<float2*>(out)[i] = o;
    }
}

__device__ __forceinline__ void red_add_v2(float* addr, float a, float b) {
    asm volatile("red.global.add.v2.f32 [%0], {%1, %2};"
                 :: "l"(addr), "f"(a), "f"(b) : "memory");
}

// Each thread handles 4 edges (coalesced int4 index loads).
__global__ void edge_force_kernel(const float* __restrict__ x,
                                  const int*   __restrict__ src,
                                  const int*   __restrict__ dst,
                                  float* __restrict__ out) {
    int t = blockIdx.x * blockDim.x + threadIdx.x;
    int e4 = t * 4;
    if (e4 >= EE) return;

    const float2* __restrict__ x2 = reinterpret_cast<const float2*>(x);

    int4 s4 = reinterpret_cast<const int4*>(src)[t];
    int4 d4 = reinterpret_cast<const int4*>(dst)[t];

    int ss[4] = {s4.x, s4.y, s4.z, s4.w};
    int dd[4] = {d4.x, d4.y, d4.z, d4.w};

    // Gather all positions first to expose MLP
    float2 xs[4], xd[4];
#pragma unroll
    for (int k = 0; k < 4; k++) {
        xs[k] = __ldg(&x2[ss[k]]);
        xd[k] = __ldg(&x2[dd[k]]);
    }

#pragma unroll
    for (int k = 0; k < 4; k++) {
        float drx = xd[k].x - xs[k].x;
        float dry = xd[k].y - xs[k].y;
        float ab  = sqrtf(drx * drx + dry * dry);
        // force magnitude = -C*P*(ab - R_C)^(P-1) = -2*(ab - 1)
        // message = force * dr / max(ab, eps)
        float inv = 1.0f / fmaxf(ab, EPSN);
        float f   = -2.0f * (ab - 1.0f) * inv;
        float mx = f * drx;
        float my = f * dry;
        red_add_v2(out + 2 * dd[k], mx, my);
    }
}

extern "C" void kernel_launch(void* const* d_in, const int* in_sizes, int n_in,
                              void* d_out, int out_size) {
    const float* x   = (const float*)d_in[0];
    const float* v   = (const float*)d_in[1];
    const int*   src = (const int*)d_in[2];
    const int*   dst = (const int*)d_in[3];
    float* out = (float*)d_out;

    // Init: out = -gamma * v  (N float2 elements)
    {
        int n = NN;
        int threads = 256;
        int blocks = (n + threads - 1) / threads;
        init_damping_kernel<<<blocks, threads>>>(v, out, n);
    }
    // Edge scatter
    {
        int nthreads_total = EE / 4;
        int threads = 256;
        int blocks = (nthreads_total + threads - 1) / threads;
        edge_force_kernel<<<blocks, threads>>>(x, src, dst, out);
    }
}